// round 1
// baseline (speedup 1.0000x reference)
#include <cuda_runtime.h>
#include <cuda_bf16.h>
#include <cstdint>

using bf16 = __nv_bfloat16;

// Problem constants
#define B_ 8
#define N_ 1024
#define D_ 512
#define H_ 8
#define DH_ 64
#define MLP_ 2048
#define ROWS_ (B_ * N_)          // 8192
#define NEGBIG (-1e10f)

// ---------------- scratch (device globals; no allocation allowed) ----------------
__device__ bf16  g_h[ROWS_ * D_];            // LN1 output
__device__ bf16  g_qkv[ROWS_ * 3 * D_];      // qkv, row-major [8192][1536]
__device__ float g_S[67108864];              // scores fp32 [b][h][n][m]
__device__ bf16  g_P[67108864];              // probs bf16
__device__ bf16  g_attn[ROWS_ * D_];         // attention output (pre-Wout)
__device__ float g_x1[ROWS_ * D_];           // x + att_out (fp32)
__device__ bf16  g_h2[ROWS_ * D_];           // LN2 output
__device__ bf16  g_ff[ROWS_ * MLP_];         // gelu(h2@W1+b1)
__device__ float g_topk[B_ * N_];            // att_topk
__device__ bf16  g_Wqkv[D_ * 3 * D_];
__device__ bf16  g_Wout[D_ * D_];
__device__ bf16  g_W1[D_ * MLP_];
__device__ bf16  g_W2[MLP_ * D_];

// ---------------- fp32 -> bf16 convert ----------------
__global__ void cvt_kernel(const float* __restrict__ s, bf16* __restrict__ d, int n) {
    int i = blockIdx.x * blockDim.x + threadIdx.x;
    if (i < n) d[i] = __float2bfloat16(s[i]);
}

// ---------------- LayerNorm: fp32 in -> bf16 out, one block (128 thr) per row ----
__global__ void __launch_bounds__(128) ln_kernel(const float* __restrict__ x,
                                                 const float* __restrict__ gam,
                                                 const float* __restrict__ bet,
                                                 bf16* __restrict__ out) {
    int row = blockIdx.x;
    int t = threadIdx.x;
    float4 a = ((const float4*)(x + (size_t)row * D_))[t];
    float s  = a.x + a.y + a.z + a.w;
    float sq = a.x * a.x + a.y * a.y + a.z * a.z + a.w * a.w;
    __shared__ float sh[8];
    #pragma unroll
    for (int o = 16; o > 0; o >>= 1) {
        s  += __shfl_down_sync(0xffffffffu, s, o);
        sq += __shfl_down_sync(0xffffffffu, sq, o);
    }
    int w = t >> 5, l = t & 31;
    if (l == 0) { sh[w] = s; sh[4 + w] = sq; }
    __syncthreads();
    if (t == 0) {
        float S = sh[0] + sh[1] + sh[2] + sh[3];
        float Q = sh[4] + sh[5] + sh[6] + sh[7];
        float mu = S * (1.0f / D_);
        float var = Q * (1.0f / D_) - mu * mu;
        sh[0] = mu; sh[1] = rsqrtf(var + 1e-5f);
    }
    __syncthreads();
    float mu = sh[0], rs = sh[1];
    float4 gv = ((const float4*)gam)[t];
    float4 bv = ((const float4*)bet)[t];
    bf16* o = out + (size_t)row * D_ + t * 4;
    ((__nv_bfloat162*)o)[0] = __floats2bfloat162_rn((a.x - mu) * rs * gv.x + bv.x,
                                                    (a.y - mu) * rs * gv.y + bv.y);
    ((__nv_bfloat162*)o)[1] = __floats2bfloat162_rn((a.z - mu) * rs * gv.z + bv.z,
                                                    (a.w - mu) * rs * gv.w + bv.w);
}

// ---------------- masked softmax: S fp32 -> P bf16, one block (128 thr) per row ---
__global__ void __launch_bounds__(128) softmax_kernel(const float* __restrict__ S,
                                                      const float* __restrict__ mask,
                                                      bf16* __restrict__ P) {
    int rid = blockIdx.x;                 // (b*H + h)*N + n
    int n = rid & (N_ - 1);
    int b = rid >> 13;                    // / (H*N)
    const float* srow = S + (size_t)rid * N_;
    const float* mrow = mask + ((size_t)b * N_ + n) * N_;
    int t = threadIdx.x;
    float v[8];
    float4 s0 = *(const float4*)(srow + t * 8);
    float4 s1 = *(const float4*)(srow + t * 8 + 4);
    float4 m0 = *(const float4*)(mrow + t * 8);
    float4 m1 = *(const float4*)(mrow + t * 8 + 4);
    v[0] = (m0.x == 1.0f) ? NEGBIG : s0.x * 0.125f;
    v[1] = (m0.y == 1.0f) ? NEGBIG : s0.y * 0.125f;
    v[2] = (m0.z == 1.0f) ? NEGBIG : s0.z * 0.125f;
    v[3] = (m0.w == 1.0f) ? NEGBIG : s0.w * 0.125f;
    v[4] = (m1.x == 1.0f) ? NEGBIG : s1.x * 0.125f;
    v[5] = (m1.y == 1.0f) ? NEGBIG : s1.y * 0.125f;
    v[6] = (m1.z == 1.0f) ? NEGBIG : s1.z * 0.125f;
    v[7] = (m1.w == 1.0f) ? NEGBIG : s1.w * 0.125f;
    float mx = v[0];
    #pragma unroll
    for (int i = 1; i < 8; i++) mx = fmaxf(mx, v[i]);
    __shared__ float red[8];
    #pragma unroll
    for (int o = 16; o > 0; o >>= 1) mx = fmaxf(mx, __shfl_xor_sync(0xffffffffu, mx, o));
    int w = t >> 5;
    if ((t & 31) == 0) red[w] = mx;
    __syncthreads();
    mx = fmaxf(fmaxf(red[0], red[1]), fmaxf(red[2], red[3]));
    float sum = 0.0f;
    #pragma unroll
    for (int i = 0; i < 8; i++) { v[i] = expf(v[i] - mx); sum += v[i]; }
    #pragma unroll
    for (int o = 16; o > 0; o >>= 1) sum += __shfl_xor_sync(0xffffffffu, sum, o);
    if ((t & 31) == 0) red[4 + w] = sum;
    __syncthreads();
    sum = red[4] + red[5] + red[6] + red[7];
    float inv = 1.0f / sum;
    bf16* prow = P + (size_t)rid * N_ + t * 8;
    ((__nv_bfloat162*)prow)[0] = __floats2bfloat162_rn(v[0] * inv, v[1] * inv);
    ((__nv_bfloat162*)prow)[1] = __floats2bfloat162_rn(v[2] * inv, v[3] * inv);
    ((__nv_bfloat162*)prow)[2] = __floats2bfloat162_rn(v[4] * inv, v[5] * inv);
    ((__nv_bfloat162*)prow)[3] = __floats2bfloat162_rn(v[6] * inv, v[7] * inv);
}

// ---------------- att_topk: mean over heads of P[b,h,0,:] ----------------
__global__ void __launch_bounds__(1024) topk_kernel(const bf16* __restrict__ P,
                                                    float* __restrict__ topk) {
    int b = blockIdx.x, m = threadIdx.x;
    float s = 0.0f;
    #pragma unroll
    for (int h = 0; h < H_; h++)
        s += __bfloat162float(P[(size_t)(b * H_ + h) * N_ * N_ + m]);
    topk[b * N_ + m] = s * (1.0f / H_);
}

// ---------------- stable descending rank -> what_to_prune + constants ------------
__global__ void __launch_bounds__(1024) prune_kernel(const float* __restrict__ topk,
                                                     float* __restrict__ out) {
    int b = blockIdx.x, m = threadIdx.x;
    __shared__ float key[N_];
    float km = (m == 0) ? __int_as_float(0xff800000) : topk[b * N_ + m];
    key[m] = km;
    __syncthreads();
    int rank = 0;
    for (int j = 0; j < N_; j++) {
        float kj = key[j];
        rank += (kj > km) || (kj == km && j < m);
    }
    // what_to_prune = ranks [959, 1023)
    if (rank >= 959 && rank < 1023) out[4194304 + b * 64 + (rank - 959)] = (float)m;
    if (m == 0) out[4194816 + b] = -1.0f;                  // what_to_merge
    if (m < 16) out[4194824 + b * 16 + m] = 0.0f;          // survived_mask
}

// ---------------- bf16 tensor-core GEMM (mma.sync m16n8k16), fused epilogues -----
// C[M,N] = A[M,K] @ B.  A row-major (lda).  B element (k,n):
//   BNMAJ=true : at B[n*ldb + k]  (n-major, e.g. K for Q@K^T)
//   BNMAJ=false: at B[k*ldb + n]  (k-major row-major weights / V)
// EPI: 0 = store bf16; 1 = store fp32; 2 = +bias[c]+resid[r*ldc+c] -> fp32;
//      3 = gelu_exact(.+bias[c]) -> bf16
template<int BN, int EPI, bool BNMAJ>
__global__ void __launch_bounds__(256) gemm_k(
    const bf16* __restrict__ A, const bf16* __restrict__ Bm, void* __restrict__ Cp,
    int M, int N, int K, int lda, int ldb, int ldc,
    long sAb, long sAh, long sBb, long sBh, long sCb, long sCh, int ZH,
    const float* __restrict__ bias, const float* __restrict__ resid)
{
    constexpr int BM = 128, BK = 32;
    constexpr int LDS = BK + 8;                  // pad: 40 halfwords
    __shared__ bf16 As[BM * LDS];
    __shared__ bf16 Bs[BN * LDS];

    int z = blockIdx.z;
    int zb = z / ZH, zh = z - zb * ZH;
    const bf16* Ab = A  + (size_t)zb * sAb + (size_t)zh * sAh;
    const bf16* Bb = Bm + (size_t)zb * sBb + (size_t)zh * sBh;
    long coff = (long)zb * sCb + (long)zh * sCh;

    int tid = threadIdx.x;
    int warp = tid >> 5, lane = tid & 31;
    int g = lane >> 2, tg = lane & 3;
    int warpM = warp & 3, warpN = warp >> 2;     // 4 x 2 warp grid
    constexpr int WTN = BN / 2;                  // warp tile N
    constexpr int MT = 2, NT = WTN / 8;

    int row0 = blockIdx.y * BM;
    int col0 = blockIdx.x * BN;

    float acc[MT][NT][4];
    #pragma unroll
    for (int a = 0; a < MT; a++)
        #pragma unroll
        for (int b2 = 0; b2 < NT; b2++)
            #pragma unroll
            for (int c = 0; c < 4; c++) acc[a][b2][c] = 0.0f;

    for (int k0 = 0; k0 < K; k0 += BK) {
        // load A tile: BM x BK, 8 bf16 per uint4
        for (int c = tid; c < BM * BK / 8; c += 256) {
            int r = c >> 2, kc = (c & 3) << 3;
            *(uint4*)(&As[r * LDS + kc]) =
                *(const uint4*)(Ab + (size_t)(row0 + r) * lda + k0 + kc);
        }
        if (BNMAJ) {
            for (int c = tid; c < BN * BK / 8; c += 256) {
                int nn = c >> 2, kc = (c & 3) << 3;
                *(uint4*)(&Bs[nn * LDS + kc]) =
                    *(const uint4*)(Bb + (size_t)(col0 + nn) * ldb + k0 + kc);
            }
        } else {
            for (int c = tid; c < BK * BN / 8; c += 256) {
                int kk = c / (BN / 8);
                int nc = (c % (BN / 8)) << 3;
                uint4 vv = *(const uint4*)(Bb + (size_t)(k0 + kk) * ldb + col0 + nc);
                bf16 tmp[8];
                *(uint4*)tmp = vv;
                #pragma unroll
                for (int i = 0; i < 8; i++) Bs[(nc + i) * LDS + kk] = tmp[i];
            }
        }
        __syncthreads();

        #pragma unroll
        for (int kk = 0; kk < BK; kk += 16) {
            uint32_t af[MT][4], bfr[NT][2];
            #pragma unroll
            for (int mt = 0; mt < MT; mt++) {
                const bf16* p = &As[(warpM * 32 + mt * 16 + g) * LDS + kk + 2 * tg];
                af[mt][0] = *(const uint32_t*)p;
                af[mt][1] = *(const uint32_t*)(p + 8 * LDS);
                af[mt][2] = *(const uint32_t*)(p + 8);
                af[mt][3] = *(const uint32_t*)(p + 8 * LDS + 8);
            }
            #pragma unroll
            for (int nt = 0; nt < NT; nt++) {
                const bf16* p = &Bs[(warpN * WTN + nt * 8 + g) * LDS + kk + 2 * tg];
                bfr[nt][0] = *(const uint32_t*)p;
                bfr[nt][1] = *(const uint32_t*)(p + 8);
            }
            #pragma unroll
            for (int mt = 0; mt < MT; mt++)
                #pragma unroll
                for (int nt = 0; nt < NT; nt++)
                    asm volatile(
                        "mma.sync.aligned.m16n8k16.row.col.f32.bf16.bf16.f32 "
                        "{%0,%1,%2,%3}, {%4,%5,%6,%7}, {%8,%9}, {%0,%1,%2,%3};\n"
                        : "+f"(acc[mt][nt][0]), "+f"(acc[mt][nt][1]),
                          "+f"(acc[mt][nt][2]), "+f"(acc[mt][nt][3])
                        : "r"(af[mt][0]), "r"(af[mt][1]), "r"(af[mt][2]), "r"(af[mt][3]),
                          "r"(bfr[nt][0]), "r"(bfr[nt][1]));
        }
        __syncthreads();
    }

    // epilogue
    #pragma unroll
    for (int mt = 0; mt < MT; mt++) {
        #pragma unroll
        for (int nt = 0; nt < NT; nt++) {
            int r = row0 + warpM * 32 + mt * 16 + g;
            int cc = col0 + warpN * WTN + nt * 8 + 2 * tg;
            #pragma unroll
            for (int hf = 0; hf < 2; hf++) {
                int rr = r + hf * 8;
                float v0 = acc[mt][nt][hf * 2 + 0];
                float v1 = acc[mt][nt][hf * 2 + 1];
                long idx = coff + (long)rr * ldc + cc;
                if (EPI == 0) {
                    *(__nv_bfloat162*)((bf16*)Cp + idx) = __floats2bfloat162_rn(v0, v1);
                } else if (EPI == 1) {
                    *(float2*)((float*)Cp + idx) = make_float2(v0, v1);
                } else if (EPI == 2) {
                    v0 += bias[cc]     + resid[(long)rr * ldc + cc];
                    v1 += bias[cc + 1] + resid[(long)rr * ldc + cc + 1];
                    *(float2*)((float*)Cp + idx) = make_float2(v0, v1);
                } else {  // EPI == 3: exact GELU
                    v0 += bias[cc];
                    v1 += bias[cc + 1];
                    v0 = 0.5f * v0 * (1.0f + erff(v0 * 0.70710678118654752f));
                    v1 = 0.5f * v1 * (1.0f + erff(v1 * 0.70710678118654752f));
                    *(__nv_bfloat162*)((bf16*)Cp + idx) = __floats2bfloat162_rn(v0, v1);
                }
            }
        }
    }
}

// ---------------- host launch ----------------
template <typename T>
static T* symaddr(const T& sym) {
    void* p = nullptr;
    cudaGetSymbolAddress(&p, sym);
    return (T*)p;
}

extern "C" void kernel_launch(void* const* d_in, const int* in_sizes, int n_in,
                              void* d_out, int out_size) {
    const float* x    = (const float*)d_in[0];
    const float* mask = (const float*)d_in[1];
    const float* Wqkv = (const float*)d_in[2];
    const float* Wout = (const float*)d_in[3];
    const float* bout = (const float*)d_in[4];
    const float* ln1g = (const float*)d_in[5];
    const float* ln1b = (const float*)d_in[6];
    const float* ln2g = (const float*)d_in[7];
    const float* ln2b = (const float*)d_in[8];
    const float* W1   = (const float*)d_in[9];
    const float* b1   = (const float*)d_in[10];
    const float* W2   = (const float*)d_in[11];
    const float* b2   = (const float*)d_in[12];

    bf16* h    = (bf16*)symaddr(g_h);
    bf16* qkv  = (bf16*)symaddr(g_qkv);
    float* S   = (float*)symaddr(g_S);
    bf16* P    = (bf16*)symaddr(g_P);
    bf16* attn = (bf16*)symaddr(g_attn);
    float* x1  = (float*)symaddr(g_x1);
    bf16* h2   = (bf16*)symaddr(g_h2);
    bf16* ff   = (bf16*)symaddr(g_ff);
    float* tk  = (float*)symaddr(g_topk);
    bf16* wqkv = (bf16*)symaddr(g_Wqkv);
    bf16* wout = (bf16*)symaddr(g_Wout);
    bf16* w1   = (bf16*)symaddr(g_W1);
    bf16* w2   = (bf16*)symaddr(g_W2);

    // weight converts
    cvt_kernel<<<(D_ * 3 * D_ + 255) / 256, 256>>>(Wqkv, wqkv, D_ * 3 * D_);
    cvt_kernel<<<(D_ * D_ + 255) / 256, 256>>>(Wout, wout, D_ * D_);
    cvt_kernel<<<(D_ * MLP_ + 255) / 256, 256>>>(W1, w1, D_ * MLP_);
    cvt_kernel<<<(MLP_ * D_ + 255) / 256, 256>>>(W2, w2, MLP_ * D_);

    // LN1
    ln_kernel<<<ROWS_, 128>>>(x, ln1g, ln1b, h);

    // qkv = h @ Wqkv          [8192,512] @ [512,1536] -> bf16 [8192,1536]
    gemm_k<128, 0, false><<<dim3(12, 64, 1), 256>>>(
        h, wqkv, qkv, ROWS_, 3 * D_, D_, D_, 3 * D_, 3 * D_,
        0, 0, 0, 0, 0, 0, 1, nullptr, nullptr);

    // S = Q @ K^T (batched over b,h): M=N=1024, K=64
    gemm_k<128, 1, true><<<dim3(8, 8, 64), 256>>>(
        qkv, qkv + 512, S, N_, N_, DH_, 1536, 1536, N_,
        1572864, 64, 1572864, 64, 8388608, 1048576, H_, nullptr, nullptr);

    // softmax (scale + mask + exp + normalize) -> P bf16
    softmax_kernel<<<B_ * H_ * N_, 128>>>(S, mask, P);

    // att_topk + prune/merge/survived
    topk_kernel<<<B_, 1024>>>(P, tk);
    prune_kernel<<<B_, 1024>>>(tk, (float*)d_out);

    // O = P @ V (batched): M=1024, N=64, K=1024
    gemm_k<64, 0, false><<<dim3(1, 8, 64), 256>>>(
        P, qkv + 1024, attn, N_, DH_, N_, N_, 1536, D_,
        8388608, 1048576, 1572864, 64, 524288, 64, H_, nullptr, nullptr);

    // x1 = x + O @ Wout + bout
    gemm_k<128, 2, false><<<dim3(4, 64, 1), 256>>>(
        attn, wout, x1, ROWS_, D_, D_, D_, D_, D_,
        0, 0, 0, 0, 0, 0, 1, bout, x);

    // LN2
    ln_kernel<<<ROWS_, 128>>>(x1, ln2g, ln2b, h2);

    // ff = gelu(h2 @ W1 + b1)
    gemm_k<128, 3, false><<<dim3(16, 64, 1), 256>>>(
        h2, w1, ff, ROWS_, MLP_, D_, D_, MLP_, MLP_,
        0, 0, 0, 0, 0, 0, 1, b1, nullptr);

    // out = x1 + ff @ W2 + b2   (first 4194304 floats of d_out)
    gemm_k<128, 2, false><<<dim3(4, 64, 1), 256>>>(
        ff, w2, d_out, ROWS_, D_, MLP_, MLP_, D_, D_,
        0, 0, 0, 0, 0, 0, 1, b2, x1);
}